// round 1
// baseline (speedup 1.0000x reference)
#include <cuda_runtime.h>
#include <math.h>

#define TOKENS 4096
#define HIDDEN 2048
#define INTER  1408
#define NE     16
#define TOPK   2
#define MAXROWS (TOKENS * TOPK)

// ---------------- scratch (static device allocations; no cudaMalloc) ---------
__device__ int   g_count[NE];
__device__ int   g_offset[NE + 1];
__device__ int   g_cursor[NE];
__device__ int   g_te[TOKENS * TOPK];     // per-token chosen experts
__device__ float g_tw[TOKENS * TOPK];     // per-token softmaxed weights
__device__ int   g_tok[MAXROWS];          // rows sorted by expert
__device__ float g_w[MAXROWS];
__device__ float g_act[(size_t)MAXROWS * INTER];  // swiglu activations (~46 MB)

// ---------------- kernel 1: zero output + counters ---------------------------
__global__ void zero_kernel(float* __restrict__ out) {
    int i = blockIdx.x * blockDim.x + threadIdx.x;
    if (i < TOKENS * HIDDEN) out[i] = 0.0f;
    if (i < NE) g_count[i] = 0;
}

// ---------------- kernel 2: routing (top-2 + softmax over the 2 logits) ------
__global__ void route_kernel(const float* __restrict__ logits) {
    int t = blockIdx.x * blockDim.x + threadIdx.x;
    if (t >= TOKENS) return;
    const float* l = logits + (size_t)t * NE;

    int i0 = 0; float m0 = l[0];
#pragma unroll
    for (int i = 1; i < NE; i++) { float x = l[i]; if (x > m0) { m0 = x; i0 = i; } }
    int i1 = (i0 == 0) ? 1 : 0; float m1 = l[i1];
#pragma unroll
    for (int i = 0; i < NE; i++) {
        if (i == i0) continue;
        float x = l[i];
        if (x > m1) { m1 = x; i1 = i; }
    }
    // softmax over [m0, m1], m0 >= m1
    float e  = expf(m1 - m0);
    float w0 = 1.0f / (1.0f + e);
    float w1 = e * w0;

    g_te[t * 2 + 0] = i0;  g_tw[t * 2 + 0] = w0;
    g_te[t * 2 + 1] = i1;  g_tw[t * 2 + 1] = w1;
    atomicAdd(&g_count[i0], 1);
    atomicAdd(&g_count[i1], 1);
}

// ---------------- kernel 3: tiny serial scan ----------------------------------
__global__ void scan_kernel() {
    if (threadIdx.x == 0) {
        int acc = 0;
        g_offset[0] = 0;
        for (int i = 0; i < NE; i++) {
            acc += g_count[i];
            g_offset[i + 1] = acc;
            g_cursor[i] = 0;
        }
    }
}

// ---------------- kernel 4: placement into per-expert row lists ---------------
__global__ void place_kernel() {
    int t = blockIdx.x * blockDim.x + threadIdx.x;
    if (t >= TOKENS) return;
#pragma unroll
    for (int k = 0; k < TOPK; k++) {
        int   e = g_te[t * 2 + k];
        float w = g_tw[t * 2 + k];
        int pos = atomicAdd(&g_cursor[e], 1);
        int idx = g_offset[e] + pos;
        g_tok[idx] = t;
        g_w[idx]   = w;
    }
}

// ---------------- kernel 5: fused gate+up grouped SGEMM + SwiGLU --------------
// Tile: BM=128, BN=64, BK=8. 256 threads, each owns 8x4 for BOTH gate and up.
__global__ __launch_bounds__(256) void gemm_gate_up(
    const float* __restrict__ hid,
    const float* __restrict__ wg,
    const float* __restrict__ wu)
{
    const int e   = blockIdx.z;
    const int cnt = g_count[e];
    const int m0  = blockIdx.y * 128;
    if (m0 >= cnt) return;
    const int n0   = blockIdx.x * 64;
    const int base = g_offset[e];

    __shared__ float As[8][128];
    __shared__ float Bgs[8][64];
    __shared__ float Bus[8][64];
    __shared__ int   toks[128];

    const int tid = threadIdx.x;
    if (tid < 128) {
        int r = m0 + tid;
        toks[tid] = (r < cnt) ? g_tok[base + r] : -1;
    }
    __syncthreads();

    // A loader: 128 rows x 8 k, one float4 per thread
    const int  ar = tid >> 1;
    const int  ak = (tid & 1) << 2;
    const int  tok = toks[ar];
    const bool avalid = (tok >= 0);
    const float* aptr = hid + (size_t)(avalid ? tok : 0) * HIDDEN + ak;

    // B loaders: 8 rows x 64 n, one float2 per thread (for each of wg, wu)
    const int br = tid >> 5;          // 0..7
    const int bc = (tid & 31) << 1;   // 0..62
    const size_t wbase = (size_t)e * HIDDEN * INTER + (size_t)br * INTER + (n0 + bc);
    const float* bg_ptr = wg + wbase;
    const float* bu_ptr = wu + wbase;

    const int tm = (tid >> 4) << 3;   // 0..120
    const int tn = (tid & 15) << 2;   // 0..60

    float accg[8][4] = {};
    float accu[8][4] = {};

    for (int k0 = 0; k0 < HIDDEN; k0 += 8) {
        float4 av = avalid ? *(const float4*)(aptr + k0) : make_float4(0, 0, 0, 0);
        float2 gv = *(const float2*)(bg_ptr + (size_t)k0 * INTER);
        float2 uv = *(const float2*)(bu_ptr + (size_t)k0 * INTER);

        As[ak + 0][ar] = av.x;  As[ak + 1][ar] = av.y;
        As[ak + 2][ar] = av.z;  As[ak + 3][ar] = av.w;
        Bgs[br][bc] = gv.x;  Bgs[br][bc + 1] = gv.y;
        Bus[br][bc] = uv.x;  Bus[br][bc + 1] = uv.y;
        __syncthreads();

#pragma unroll
        for (int k = 0; k < 8; k++) {
            float a[8], bg[4], bu[4];
#pragma unroll
            for (int i = 0; i < 8; i++) a[i] = As[k][tm + i];
#pragma unroll
            for (int j = 0; j < 4; j++) { bg[j] = Bgs[k][tn + j]; bu[j] = Bus[k][tn + j]; }
#pragma unroll
            for (int i = 0; i < 8; i++)
#pragma unroll
                for (int j = 0; j < 4; j++) {
                    accg[i][j] += a[i] * bg[j];
                    accu[i][j] += a[i] * bu[j];
                }
        }
        __syncthreads();
    }

    // SwiGLU epilogue: act = silu(g) * u
#pragma unroll
    for (int i = 0; i < 8; i++) {
        int m = m0 + tm + i;
        if (m >= cnt) continue;
        float* dst = g_act + (size_t)(base + m) * INTER + n0 + tn;
#pragma unroll
        for (int j = 0; j < 4; j++) {
            float g = accg[i][j];
            float u = accu[i][j];
            float s = g / (1.0f + expf(-g));   // silu
            dst[j] = s * u;
        }
    }
}

// ---------------- kernel 6: down grouped SGEMM + weighted scatter -------------
// Tile: BM=128, BN=128, BK=8. 256 threads, each owns 8x8.
__global__ __launch_bounds__(256) void gemm_down(
    const float* __restrict__ wd, float* __restrict__ out)
{
    const int e   = blockIdx.z;
    const int cnt = g_count[e];
    const int m0  = blockIdx.y * 128;
    if (m0 >= cnt) return;
    const int n0   = blockIdx.x * 128;
    const int base = g_offset[e];

    __shared__ float As[8][128];
    __shared__ float Bs[8][128];

    const int tid = threadIdx.x;
    const int  ar = tid >> 1;
    const int  ak = (tid & 1) << 2;
    const int  arow = m0 + ar;
    const bool avalid = (arow < cnt);
    const float* aptr = g_act + (size_t)(base + (avalid ? arow : 0)) * INTER + ak;

    const int br = tid >> 5;          // 0..7
    const int bc = (tid & 31) << 2;   // 0..124
    const float* bptr = wd + (size_t)e * INTER * HIDDEN + (size_t)br * HIDDEN + n0 + bc;

    const int tm = (tid >> 4) << 3;
    const int tn = (tid & 15) << 3;

    float acc[8][8] = {};

    for (int k0 = 0; k0 < INTER; k0 += 8) {
        float4 av = avalid ? *(const float4*)(aptr + k0) : make_float4(0, 0, 0, 0);
        float4 bv = *(const float4*)(bptr + (size_t)k0 * HIDDEN);

        As[ak + 0][ar] = av.x;  As[ak + 1][ar] = av.y;
        As[ak + 2][ar] = av.z;  As[ak + 3][ar] = av.w;
        *(float4*)&Bs[br][bc] = bv;
        __syncthreads();

#pragma unroll
        for (int k = 0; k < 8; k++) {
            float a[8], b[8];
            *(float4*)&a[0] = *(const float4*)&As[k][tm];
            *(float4*)&a[4] = *(const float4*)&As[k][tm + 4];
            *(float4*)&b[0] = *(const float4*)&Bs[k][tn];
            *(float4*)&b[4] = *(const float4*)&Bs[k][tn + 4];
#pragma unroll
            for (int i = 0; i < 8; i++)
#pragma unroll
                for (int j = 0; j < 8; j++) acc[i][j] += a[i] * b[j];
        }
        __syncthreads();
    }

    // weighted scatter into the shared output (2 contributions per token)
#pragma unroll
    for (int i = 0; i < 8; i++) {
        int m = m0 + tm + i;
        if (m >= cnt) continue;
        int   t = g_tok[base + m];
        float w = g_w[base + m];
        float* dst = out + (size_t)t * HIDDEN + n0 + tn;
#pragma unroll
        for (int j = 0; j < 8; j++) atomicAdd(&dst[j], w * acc[i][j]);
    }
}

// ---------------- launch --------------------------------------------------------
extern "C" void kernel_launch(void* const* d_in, const int* in_sizes, int n_in,
                              void* d_out, int out_size) {
    (void)in_sizes; (void)n_in; (void)out_size;
    const float* hidden = (const float*)d_in[0];
    const float* logits = (const float*)d_in[1];
    const float* wg     = (const float*)d_in[2];
    const float* wu     = (const float*)d_in[3];
    const float* wd     = (const float*)d_in[4];
    float* out = (float*)d_out;

    zero_kernel<<<(TOKENS * HIDDEN + 255) / 256, 256>>>(out);
    route_kernel<<<(TOKENS + 255) / 256, 256>>>(logits);
    scan_kernel<<<1, 32>>>();
    place_kernel<<<(TOKENS + 255) / 256, 256>>>();

    dim3 g1(INTER / 64, (TOKENS + 127) / 128, NE);   // (22, 32, 16)
    gemm_gate_up<<<g1, 256>>>(hidden, wg, wu);

    dim3 g2(HIDDEN / 128, (TOKENS + 127) / 128, NE); // (16, 32, 16)
    gemm_down<<<g2, 256>>>(wd, out);
}

// round 2
// speedup vs baseline: 1.0454x; 1.0454x over previous
#include <cuda_runtime.h>
#include <math.h>

#define TOKENS 4096
#define HIDDEN 2048
#define INTER  1408
#define NE     16
#define TOPK   2
#define MAXROWS (TOKENS * TOPK)

typedef unsigned long long ull;

// ---------------- scratch ----------------------------------------------------
__device__ int   g_count[NE];
__device__ int   g_offset[NE + 1];
__device__ int   g_cursor[NE];
__device__ int   g_te[TOKENS * TOPK];
__device__ float g_tw[TOKENS * TOPK];
__device__ int   g_tok[MAXROWS];
__device__ float g_w[MAXROWS];
__device__ float g_act[(size_t)MAXROWS * INTER];  // ~46 MB

// packed fp32x2 FMA (Blackwell FFMA2, only reachable via PTX)
__device__ __forceinline__ void fma2(ull& d, ull a, ull b) {
    asm("fma.rn.f32x2 %0, %1, %2, %0;" : "+l"(d) : "l"(a), "l"(b));
}
__device__ __forceinline__ float2 ull2f2(ull v) {
    float2 r;
    asm("mov.b64 {%0,%1}, %2;" : "=f"(r.x), "=f"(r.y) : "l"(v));
    return r;
}

// ---------------- kernel 1: zero output + counters ---------------------------
__global__ void zero_kernel(float* __restrict__ out) {
    int i = blockIdx.x * blockDim.x + threadIdx.x;
    if (i < TOKENS * HIDDEN) out[i] = 0.0f;
    if (i < NE) g_count[i] = 0;
}

// ---------------- kernel 2: routing ------------------------------------------
__global__ void route_kernel(const float* __restrict__ logits) {
    int t = blockIdx.x * blockDim.x + threadIdx.x;
    if (t >= TOKENS) return;
    const float* l = logits + (size_t)t * NE;

    int i0 = 0; float m0 = l[0];
#pragma unroll
    for (int i = 1; i < NE; i++) { float x = l[i]; if (x > m0) { m0 = x; i0 = i; } }
    int i1 = (i0 == 0) ? 1 : 0; float m1 = l[i1];
#pragma unroll
    for (int i = 0; i < NE; i++) {
        if (i == i0) continue;
        float x = l[i];
        if (x > m1) { m1 = x; i1 = i; }
    }
    float e  = expf(m1 - m0);
    float w0 = 1.0f / (1.0f + e);
    float w1 = e * w0;

    g_te[t * 2 + 0] = i0;  g_tw[t * 2 + 0] = w0;
    g_te[t * 2 + 1] = i1;  g_tw[t * 2 + 1] = w1;
    atomicAdd(&g_count[i0], 1);
    atomicAdd(&g_count[i1], 1);
}

// ---------------- kernel 3: tiny serial scan ----------------------------------
__global__ void scan_kernel() {
    if (threadIdx.x == 0) {
        int acc = 0;
        g_offset[0] = 0;
        for (int i = 0; i < NE; i++) {
            acc += g_count[i];
            g_offset[i + 1] = acc;
            g_cursor[i] = 0;
        }
    }
}

// ---------------- kernel 4: placement -----------------------------------------
__global__ void place_kernel() {
    int t = blockIdx.x * blockDim.x + threadIdx.x;
    if (t >= TOKENS) return;
#pragma unroll
    for (int k = 0; k < TOPK; k++) {
        int   e = g_te[t * 2 + k];
        float w = g_tw[t * 2 + k];
        int pos = atomicAdd(&g_cursor[e], 1);
        int idx = g_offset[e] + pos;
        g_tok[idx] = t;
        g_w[idx]   = w;
    }
}

// ---------------- kernel 5: fused gate+up GEMM (FFMA2, double buffered) -------
// BM=128, BN=64(x2 matrices), BK=8, 256 threads, thread tile 8m x 4n per matrix.
__global__ __launch_bounds__(256, 2) void gemm_gate_up(
    const float* __restrict__ hid,
    const float* __restrict__ wg,
    const float* __restrict__ wu)
{
    const int e   = blockIdx.z;
    const int cnt = g_count[e];
    const int m0  = blockIdx.y * 128;
    if (m0 >= cnt) return;
    const int n0   = blockIdx.x * 64;
    const int base = g_offset[e];

    __shared__ float2 As[2][8][128];   // duplicated pairs {a,a}; 16KB
    __shared__ float  Bgs[2][8][64];   // 4KB
    __shared__ float  Bus[2][8][64];   // 4KB
    __shared__ int    toks[128];

    const int tid = threadIdx.x;
    if (tid < 128) {
        int r = m0 + tid;
        toks[tid] = (r < cnt) ? g_tok[base + r] : -1;
    }
    __syncthreads();

    // A loader: row ar, 4 consecutive k
    const int  ar = tid >> 1;
    const int  ak = (tid & 1) << 2;
    const int  tok = toks[ar];
    const bool avalid = (tok >= 0);
    const float* aptr = hid + (size_t)(avalid ? tok : 0) * HIDDEN + ak;

    // B loaders: 8 rows x 64 n, float2 per thread per matrix
    const int br = tid >> 5;          // 0..7
    const int bc = (tid & 31) << 1;   // 0..62
    const size_t wbase = (size_t)e * HIDDEN * INTER + (size_t)br * INTER + (n0 + bc);
    const float* bg_ptr = wg + wbase;
    const float* bu_ptr = wu + wbase;

    const int tm = (tid >> 4) << 3;   // 0..120
    const int tn = (tid & 15) << 2;   // 0..60

    ull accg[8][2] = {};
    ull accu[8][2] = {};

    // ---- prologue: load tile 0 into buf 0 ----
    float4 av = avalid ? *(const float4*)(aptr) : make_float4(0, 0, 0, 0);
    float2 gv = *(const float2*)(bg_ptr);
    float2 uv = *(const float2*)(bu_ptr);
    {
        As[0][ak + 0][ar] = make_float2(av.x, av.x);
        As[0][ak + 1][ar] = make_float2(av.y, av.y);
        As[0][ak + 2][ar] = make_float2(av.z, av.z);
        As[0][ak + 3][ar] = make_float2(av.w, av.w);
        Bgs[0][br][bc] = gv.x;  Bgs[0][br][bc + 1] = gv.y;
        Bus[0][br][bc] = uv.x;  Bus[0][br][bc + 1] = uv.y;
    }
    __syncthreads();

    int buf = 0;
    const int NT = HIDDEN / 8;   // 256 k-tiles
    for (int t = 1; t < NT; t++) {
        const int k0 = t * 8;
        // prefetch next tile into registers
        av = avalid ? *(const float4*)(aptr + k0) : make_float4(0, 0, 0, 0);
        gv = *(const float2*)(bg_ptr + (size_t)k0 * INTER);
        uv = *(const float2*)(bu_ptr + (size_t)k0 * INTER);

        // compute current buffer
#pragma unroll
        for (int k = 0; k < 8; k++) {
            const ull* ap = (const ull*)&As[buf][k][tm];
            ull a2[8];
#pragma unroll
            for (int i = 0; i < 4; i++) {
                ulonglong2 v = ((const ulonglong2*)ap)[i];
                a2[2 * i] = v.x; a2[2 * i + 1] = v.y;
            }
            ulonglong2 bg = *(const ulonglong2*)&Bgs[buf][k][tn];
            ulonglong2 bu = *(const ulonglong2*)&Bus[buf][k][tn];
#pragma unroll
            for (int i = 0; i < 8; i++) {
                fma2(accg[i][0], a2[i], bg.x);
                fma2(accg[i][1], a2[i], bg.y);
                fma2(accu[i][0], a2[i], bu.x);
                fma2(accu[i][1], a2[i], bu.y);
            }
        }

        // store prefetched tile into other buffer
        const int nb = buf ^ 1;
        As[nb][ak + 0][ar] = make_float2(av.x, av.x);
        As[nb][ak + 1][ar] = make_float2(av.y, av.y);
        As[nb][ak + 2][ar] = make_float2(av.z, av.z);
        As[nb][ak + 3][ar] = make_float2(av.w, av.w);
        Bgs[nb][br][bc] = gv.x;  Bgs[nb][br][bc + 1] = gv.y;
        Bus[nb][br][bc] = uv.x;  Bus[nb][br][bc + 1] = uv.y;
        __syncthreads();
        buf = nb;
    }
    // last tile
#pragma unroll
    for (int k = 0; k < 8; k++) {
        const ull* ap = (const ull*)&As[buf][k][tm];
        ull a2[8];
#pragma unroll
        for (int i = 0; i < 4; i++) {
            ulonglong2 v = ((const ulonglong2*)ap)[i];
            a2[2 * i] = v.x; a2[2 * i + 1] = v.y;
        }
        ulonglong2 bg = *(const ulonglong2*)&Bgs[buf][k][tn];
        ulonglong2 bu = *(const ulonglong2*)&Bus[buf][k][tn];
#pragma unroll
        for (int i = 0; i < 8; i++) {
            fma2(accg[i][0], a2[i], bg.x);
            fma2(accg[i][1], a2[i], bg.y);
            fma2(accu[i][0], a2[i], bu.x);
            fma2(accu[i][1], a2[i], bu.y);
        }
    }

    // SwiGLU epilogue
#pragma unroll
    for (int i = 0; i < 8; i++) {
        int m = m0 + tm + i;
        if (m >= cnt) continue;
        float* dst = g_act + (size_t)(base + m) * INTER + n0 + tn;
        float4 o;
        float2 g0 = ull2f2(accg[i][0]), g1 = ull2f2(accg[i][1]);
        float2 u0 = ull2f2(accu[i][0]), u1 = ull2f2(accu[i][1]);
        o.x = (g0.x / (1.0f + expf(-g0.x))) * u0.x;
        o.y = (g0.y / (1.0f + expf(-g0.y))) * u0.y;
        o.z = (g1.x / (1.0f + expf(-g1.x))) * u1.x;
        o.w = (g1.y / (1.0f + expf(-g1.y))) * u1.y;
        *(float4*)dst = o;
    }
}

// ---------------- kernel 6: down GEMM (FFMA2, double buffered) + scatter ------
// BM=128, BN=128, BK=8, 256 threads, thread tile 8m x 8n.
__global__ __launch_bounds__(256, 2) void gemm_down(
    const float* __restrict__ wd, float* __restrict__ out)
{
    const int e   = blockIdx.z;
    const int cnt = g_count[e];
    const int m0  = blockIdx.y * 128;
    if (m0 >= cnt) return;
    const int n0   = blockIdx.x * 128;
    const int base = g_offset[e];

    __shared__ float2 As[2][8][128];   // duplicated pairs; 16KB
    __shared__ float  Bs[2][8][128];   // 8KB

    const int tid = threadIdx.x;
    const int  ar = tid >> 1;
    const int  ak = (tid & 1) << 2;
    const int  arow = m0 + ar;
    const bool avalid = (arow < cnt);
    const float* aptr = g_act + (size_t)(base + (avalid ? arow : 0)) * INTER + ak;

    const int br = tid >> 5;          // 0..7
    const int bc = (tid & 31) << 2;   // 0..124
    const float* bptr = wd + (size_t)e * INTER * HIDDEN + (size_t)br * HIDDEN + n0 + bc;

    const int tm = (tid >> 4) << 3;
    const int tn = (tid & 15) << 3;

    ull acc[8][4] = {};

    // prologue
    float4 av = avalid ? *(const float4*)(aptr) : make_float4(0, 0, 0, 0);
    float4 bv = *(const float4*)(bptr);
    {
        As[0][ak + 0][ar] = make_float2(av.x, av.x);
        As[0][ak + 1][ar] = make_float2(av.y, av.y);
        As[0][ak + 2][ar] = make_float2(av.z, av.z);
        As[0][ak + 3][ar] = make_float2(av.w, av.w);
        *(float4*)&Bs[0][br][bc] = bv;
    }
    __syncthreads();

    int buf = 0;
    const int NT = INTER / 8;    // 176 k-tiles
    for (int t = 1; t < NT; t++) {
        const int k0 = t * 8;
        av = avalid ? *(const float4*)(aptr + k0) : make_float4(0, 0, 0, 0);
        bv = *(const float4*)(bptr + (size_t)k0 * HIDDEN);

#pragma unroll
        for (int k = 0; k < 8; k++) {
            const ull* ap = (const ull*)&As[buf][k][tm];
            ull a2[8];
#pragma unroll
            for (int i = 0; i < 4; i++) {
                ulonglong2 v = ((const ulonglong2*)ap)[i];
                a2[2 * i] = v.x; a2[2 * i + 1] = v.y;
            }
            ulonglong2 b01 = *(const ulonglong2*)&Bs[buf][k][tn];
            ulonglong2 b23 = *(const ulonglong2*)&Bs[buf][k][tn + 4];
#pragma unroll
            for (int i = 0; i < 8; i++) {
                fma2(acc[i][0], a2[i], b01.x);
                fma2(acc[i][1], a2[i], b01.y);
                fma2(acc[i][2], a2[i], b23.x);
                fma2(acc[i][3], a2[i], b23.y);
            }
        }

        const int nb = buf ^ 1;
        As[nb][ak + 0][ar] = make_float2(av.x, av.x);
        As[nb][ak + 1][ar] = make_float2(av.y, av.y);
        As[nb][ak + 2][ar] = make_float2(av.z, av.z);
        As[nb][ak + 3][ar] = make_float2(av.w, av.w);
        *(float4*)&Bs[nb][br][bc] = bv;
        __syncthreads();
        buf = nb;
    }
#pragma unroll
    for (int k = 0; k < 8; k++) {
        const ull* ap = (const ull*)&As[buf][k][tm];
        ull a2[8];
#pragma unroll
        for (int i = 0; i < 4; i++) {
            ulonglong2 v = ((const ulonglong2*)ap)[i];
            a2[2 * i] = v.x; a2[2 * i + 1] = v.y;
        }
        ulonglong2 b01 = *(const ulonglong2*)&Bs[buf][k][tn];
        ulonglong2 b23 = *(const ulonglong2*)&Bs[buf][k][tn + 4];
#pragma unroll
        for (int i = 0; i < 8; i++) {
            fma2(acc[i][0], a2[i], b01.x);
            fma2(acc[i][1], a2[i], b01.y);
            fma2(acc[i][2], a2[i], b23.x);
            fma2(acc[i][3], a2[i], b23.y);
        }
    }

    // weighted scatter (2 expert contributions per token row)
#pragma unroll
    for (int i = 0; i < 8; i++) {
        int m = m0 + tm + i;
        if (m >= cnt) continue;
        int   t = g_tok[base + m];
        float w = g_w[base + m];
        float* dst = out + (size_t)t * HIDDEN + n0 + tn;
#pragma unroll
        for (int j = 0; j < 4; j++) {
            float2 v = ull2f2(acc[i][j]);
            atomicAdd(&dst[2 * j + 0], w * v.x);
            atomicAdd(&dst[2 * j + 1], w * v.y);
        }
    }
}

// ---------------- launch --------------------------------------------------------
extern "C" void kernel_launch(void* const* d_in, const int* in_sizes, int n_in,
                              void* d_out, int out_size) {
    (void)in_sizes; (void)n_in; (void)out_size;
    const float* hidden = (const float*)d_in[0];
    const float* logits = (const float*)d_in[1];
    const float* wg     = (const float*)d_in[2];
    const float* wu     = (const float*)d_in[3];
    const float* wd     = (const float*)d_in[4];
    float* out = (float*)d_out;

    zero_kernel<<<(TOKENS * HIDDEN + 255) / 256, 256>>>(out);
    route_kernel<<<(TOKENS + 255) / 256, 256>>>(logits);
    scan_kernel<<<1, 32>>>();
    place_kernel<<<(TOKENS + 255) / 256, 256>>>();

    dim3 g1(INTER / 64, (TOKENS + 127) / 128, NE);   // (22, 32, 16)
    gemm_gate_up<<<g1, 256>>>(hidden, wg, wu);

    dim3 g2(HIDDEN / 128, (TOKENS + 127) / 128, NE); // (16, 32, 16)
    gemm_down<<<g2, 256>>>(wd, out);
}

// round 6
// speedup vs baseline: 1.7131x; 1.6387x over previous
#include <cuda_runtime.h>
#include <cuda_bf16.h>
#include <mma.h>
#include <math.h>
#include <stdint.h>

using namespace nvcuda;

#define TOKENS 4096
#define HIDDEN 2048
#define INTER  1408
#define NE     16
#define TOPK   2
#define MAXROWS (TOKENS * TOPK)

// ---------------- scratch (same footprint class as passing round 2) -----------
__device__ int   g_count[NE];
__device__ int   g_offset[NE + 1];
__device__ int   g_cursor[NE];
__device__ int   g_te[TOKENS * TOPK];
__device__ float g_tw[TOKENS * TOPK];
__device__ int   g_tok[MAXROWS];
__device__ float g_w[MAXROWS];
__device__ __align__(128) float g_act[(size_t)MAXROWS * INTER];  // ~46 MB fp32

// ---------------- kernel 1: zero output + counters (round-2 verbatim) ---------
__global__ void zero_kernel(float* __restrict__ out) {
    int i = blockIdx.x * blockDim.x + threadIdx.x;
    if (i < TOKENS * HIDDEN) out[i] = 0.0f;
    if (i < NE) g_count[i] = 0;
}

// ---------------- kernel 2: routing (round-2 verbatim) -------------------------
__global__ void route_kernel(const float* __restrict__ logits) {
    int t = blockIdx.x * blockDim.x + threadIdx.x;
    if (t >= TOKENS) return;
    const float* l = logits + (size_t)t * NE;
    int i0 = 0; float m0 = l[0];
#pragma unroll
    for (int i = 1; i < NE; i++) { float x = l[i]; if (x > m0) { m0 = x; i0 = i; } }
    int i1 = (i0 == 0) ? 1 : 0; float m1 = l[i1];
#pragma unroll
    for (int i = 0; i < NE; i++) {
        if (i == i0) continue;
        float x = l[i];
        if (x > m1) { m1 = x; i1 = i; }
    }
    float e  = expf(m1 - m0);
    float w0 = 1.0f / (1.0f + e);
    float w1 = e * w0;
    g_te[t * 2 + 0] = i0;  g_tw[t * 2 + 0] = w0;
    g_te[t * 2 + 1] = i1;  g_tw[t * 2 + 1] = w1;
    atomicAdd(&g_count[i0], 1);
    atomicAdd(&g_count[i1], 1);
}

// ---------------- kernel 3: tiny serial scan (round-2 verbatim) ---------------
__global__ void scan_kernel() {
    if (threadIdx.x == 0) {
        int acc = 0;
        g_offset[0] = 0;
        for (int i = 0; i < NE; i++) {
            acc += g_count[i];
            g_offset[i + 1] = acc;
            g_cursor[i] = 0;
        }
    }
}

// ---------------- kernel 4: placement (round-2 verbatim) ----------------------
__global__ void place_kernel() {
    int t = blockIdx.x * blockDim.x + threadIdx.x;
    if (t >= TOKENS) return;
#pragma unroll
    for (int k = 0; k < TOPK; k++) {
        int   e = g_te[t * 2 + k];
        float w = g_tw[t * 2 + k];
        int pos = atomicAdd(&g_cursor[e], 1);
        int idx = g_offset[e] + pos;
        g_tok[idx] = t;
        g_w[idx]   = w;
    }
}

// ---------------- hi/lo split helper -------------------------------------------
__device__ __forceinline__ void split4(float4 v,
                                       __nv_bfloat16* hi, __nv_bfloat16* lo) {
    __nv_bfloat16 hx = __float2bfloat16(v.x);
    __nv_bfloat16 hy = __float2bfloat16(v.y);
    __nv_bfloat16 hz = __float2bfloat16(v.z);
    __nv_bfloat16 hw = __float2bfloat16(v.w);
    hi[0] = hx; hi[1] = hy; hi[2] = hz; hi[3] = hw;
    lo[0] = __float2bfloat16(v.x - __bfloat162float(hx));
    lo[1] = __float2bfloat16(v.y - __bfloat162float(hy));
    lo[2] = __float2bfloat16(v.z - __bfloat162float(hz));
    lo[3] = __float2bfloat16(v.w - __bfloat162float(hw));
}

typedef wmma::fragment<wmma::matrix_a, 16, 16, 16, __nv_bfloat16, wmma::row_major> FragA;
typedef wmma::fragment<wmma::matrix_b, 16, 16, 16, __nv_bfloat16, wmma::row_major> FragB;
typedef wmma::fragment<wmma::accumulator, 16, 16, 16, float> FragC;

// ================ GEMM1: gate+up, wmma bf16x3 ===================================
// BM=128, BN=64, BK=32. 8 warps: 4(m) x 2(n), warp tile 32x32.
// smem layout (bytes):
//   toks  @ 0      (512)
//   Ahi   @ 512    128*40*2 = 10240
//   Alo   @ 10752  10240
//   Bgh   @ 20992  32*72*2 = 4608
//   Bgl   @ 25600  4608
//   Buh   @ 30208  4608
//   Bul   @ 34816  4608    -> end 39424
//   epilogue staging reuses @512 (per-warp 16*20*4 = 1280)
#define LDA 40
#define LDB 72
#define G1_SMEM 39424

__global__ __launch_bounds__(256) void gemm1_wmma(
    const float* __restrict__ hid,
    const float* __restrict__ wg,
    const float* __restrict__ wu)
{
    const int e   = blockIdx.z;
    const int cnt = g_count[e];
    const int m0  = blockIdx.y * 128;
    if (m0 >= cnt) return;
    const int n0   = blockIdx.x * 64;
    const int base = g_offset[e];

    extern __shared__ char sm[];
    int* toks = (int*)sm;
    __nv_bfloat16* Ahi = (__nv_bfloat16*)(sm + 512);
    __nv_bfloat16* Alo = (__nv_bfloat16*)(sm + 10752);
    __nv_bfloat16* Bgh = (__nv_bfloat16*)(sm + 20992);
    __nv_bfloat16* Bgl = (__nv_bfloat16*)(sm + 25600);
    __nv_bfloat16* Buh = (__nv_bfloat16*)(sm + 30208);
    __nv_bfloat16* Bul = (__nv_bfloat16*)(sm + 34816);

    const int tid  = threadIdx.x;
    const int wid  = tid >> 5, lane = tid & 31;
    const int wm   = (wid & 3) * 32;
    const int wn   = (wid >> 2) * 32;

    if (tid < 128) {
        int r = m0 + tid;
        toks[tid] = g_tok[base + ((r < cnt) ? r : 0)];
    }
    __syncthreads();

    FragC accg[2][2], accu[2][2];
#pragma unroll
    for (int mt = 0; mt < 2; mt++)
#pragma unroll
        for (int nt = 0; nt < 2; nt++) {
            wmma::fill_fragment(accg[mt][nt], 0.0f);
            wmma::fill_fragment(accu[mt][nt], 0.0f);
        }

    // prefetch registers (raw fp32; hi/lo derived at store time)
    float4 pfA[4], pfG[2], pfU[2];
    const int a_row = tid >> 1;            // unused placeholder removed below
    (void)a_row;

    auto LOADG = [&](int k0) {
#pragma unroll
        for (int it = 0; it < 4; it++) {
            int idx = tid + it * 256;
            int row = idx >> 3, c4 = idx & 7;
            pfA[it] = *(const float4*)(hid + (size_t)toks[row] * HIDDEN + k0 + c4 * 4);
        }
#pragma unroll
        for (int it = 0; it < 2; it++) {
            int idx = tid + it * 256;
            int row = idx >> 4, c4 = idx & 15;
            size_t off = (size_t)e * HIDDEN * INTER + (size_t)(k0 + row) * INTER + n0 + c4 * 4;
            pfG[it] = *(const float4*)(wg + off);
            pfU[it] = *(const float4*)(wu + off);
        }
    };
    auto STORES = [&]() {
#pragma unroll
        for (int it = 0; it < 4; it++) {
            int idx = tid + it * 256;
            int row = idx >> 3, c4 = idx & 7;
            split4(pfA[it], Ahi + row * LDA + c4 * 4, Alo + row * LDA + c4 * 4);
        }
#pragma unroll
        for (int it = 0; it < 2; it++) {
            int idx = tid + it * 256;
            int row = idx >> 4, c4 = idx & 15;
            split4(pfG[it], Bgh + row * LDB + c4 * 4, Bgl + row * LDB + c4 * 4);
            split4(pfU[it], Buh + row * LDB + c4 * 4, Bul + row * LDB + c4 * 4);
        }
    };

    LOADG(0);
    const int NS = HIDDEN / 32;   // 64
    for (int s = 0; s < NS; s++) {
        STORES();
        __syncthreads();
        if (s + 1 < NS) LOADG((s + 1) * 32);
#pragma unroll
        for (int kk = 0; kk < 32; kk += 16) {
            FragA ah[2], al[2];
#pragma unroll
            for (int mt = 0; mt < 2; mt++) {
                wmma::load_matrix_sync(ah[mt], Ahi + (wm + mt * 16) * LDA + kk, LDA);
                wmma::load_matrix_sync(al[mt], Alo + (wm + mt * 16) * LDA + kk, LDA);
            }
#pragma unroll
            for (int nt = 0; nt < 2; nt++) {
                FragB bh, bl;
                const int bcol = wn + nt * 16;
                wmma::load_matrix_sync(bh, Bgh + kk * LDB + bcol, LDB);
                wmma::load_matrix_sync(bl, Bgl + kk * LDB + bcol, LDB);
#pragma unroll
                for (int mt = 0; mt < 2; mt++) {
                    wmma::mma_sync(accg[mt][nt], ah[mt], bh, accg[mt][nt]);
                    wmma::mma_sync(accg[mt][nt], al[mt], bh, accg[mt][nt]);
                    wmma::mma_sync(accg[mt][nt], ah[mt], bl, accg[mt][nt]);
                }
                wmma::load_matrix_sync(bh, Buh + kk * LDB + bcol, LDB);
                wmma::load_matrix_sync(bl, Bul + kk * LDB + bcol, LDB);
#pragma unroll
                for (int mt = 0; mt < 2; mt++) {
                    wmma::mma_sync(accu[mt][nt], ah[mt], bh, accu[mt][nt]);
                    wmma::mma_sync(accu[mt][nt], al[mt], bh, accu[mt][nt]);
                    wmma::mma_sync(accu[mt][nt], ah[mt], bl, accu[mt][nt]);
                }
            }
        }
        __syncthreads();
    }

    // epilogue: swiglu in fragments (same-layout elementwise), staged stores
    float* stg = (float*)(sm + 512) + wid * 320;   // 16x20 per warp
#pragma unroll
    for (int mt = 0; mt < 2; mt++)
#pragma unroll
        for (int nt = 0; nt < 2; nt++) {
            FragC& G = accg[mt][nt];
            FragC& U = accu[mt][nt];
#pragma unroll
            for (int i = 0; i < G.num_elements; i++) {
                float g = G.x[i];
                G.x[i] = (g / (1.0f + __expf(-g))) * U.x[i];
            }
            wmma::store_matrix_sync(stg, G, 20, wmma::mem_row_major);
            __syncwarp();
            for (int i = lane; i < 256; i += 32) {
                int r = i >> 4, c = i & 15;
                int m = m0 + wm + mt * 16 + r;
                if (m < cnt)
                    g_act[(size_t)(base + m) * INTER + n0 + wn + nt * 16 + c] = stg[r * 20 + c];
            }
            __syncwarp();
        }
}

// ================ GEMM2: down, wmma bf16x3 + weighted scatter ===================
// smem: Ahi @0 (10240) | Alo @10240 | Bh @20480 (4608) | Bl @25088 -> 29696
// staging reuses @0.
#define G2_SMEM 29696

__global__ __launch_bounds__(256) void gemm2_wmma(
    const float* __restrict__ wd, float* __restrict__ out)
{
    const int e   = blockIdx.z;
    const int cnt = g_count[e];
    const int m0  = blockIdx.y * 128;
    if (m0 >= cnt) return;
    const int n0   = blockIdx.x * 64;
    const int base = g_offset[e];

    extern __shared__ char sm[];
    __nv_bfloat16* Ahi = (__nv_bfloat16*)(sm);
    __nv_bfloat16* Alo = (__nv_bfloat16*)(sm + 10240);
    __nv_bfloat16* Bh  = (__nv_bfloat16*)(sm + 20480);
    __nv_bfloat16* Bl  = (__nv_bfloat16*)(sm + 25088);

    const int tid  = threadIdx.x;
    const int wid  = tid >> 5, lane = tid & 31;
    const int wm   = (wid & 3) * 32;
    const int wn   = (wid >> 2) * 32;

    FragC acc[2][2];
#pragma unroll
    for (int mt = 0; mt < 2; mt++)
#pragma unroll
        for (int nt = 0; nt < 2; nt++) wmma::fill_fragment(acc[mt][nt], 0.0f);

    // per-thread clamped A rows for its 4 load slots
    int arows[4];
#pragma unroll
    for (int it = 0; it < 4; it++) {
        int idx = tid + it * 256;
        int row = idx >> 3;
        int m = m0 + row;
        arows[it] = base + ((m < cnt) ? m : 0);
    }

    float4 pfA[4], pfB[2];
    auto LOADG = [&](int k0) {
#pragma unroll
        for (int it = 0; it < 4; it++) {
            int idx = tid + it * 256;
            int c4 = idx & 7;
            pfA[it] = *(const float4*)(g_act + (size_t)arows[it] * INTER + k0 + c4 * 4);
        }
#pragma unroll
        for (int it = 0; it < 2; it++) {
            int idx = tid + it * 256;
            int row = idx >> 4, c4 = idx & 15;
            pfB[it] = *(const float4*)(wd + (size_t)e * INTER * HIDDEN +
                                       (size_t)(k0 + row) * HIDDEN + n0 + c4 * 4);
        }
    };
    auto STORES = [&]() {
#pragma unroll
        for (int it = 0; it < 4; it++) {
            int idx = tid + it * 256;
            int row = idx >> 3, c4 = idx & 7;
            split4(pfA[it], Ahi + row * LDA + c4 * 4, Alo + row * LDA + c4 * 4);
        }
#pragma unroll
        for (int it = 0; it < 2; it++) {
            int idx = tid + it * 256;
            int row = idx >> 4, c4 = idx & 15;
            split4(pfB[it], Bh + row * LDB + c4 * 4, Bl + row * LDB + c4 * 4);
        }
    };

    LOADG(0);
    const int NS = INTER / 32;   // 44
    for (int s = 0; s < NS; s++) {
        STORES();
        __syncthreads();
        if (s + 1 < NS) LOADG((s + 1) * 32);
#pragma unroll
        for (int kk = 0; kk < 32; kk += 16) {
            FragA ah[2], al[2];
#pragma unroll
            for (int mt = 0; mt < 2; mt++) {
                wmma::load_matrix_sync(ah[mt], Ahi + (wm + mt * 16) * LDA + kk, LDA);
                wmma::load_matrix_sync(al[mt], Alo + (wm + mt * 16) * LDA + kk, LDA);
            }
#pragma unroll
            for (int nt = 0; nt < 2; nt++) {
                FragB bh, bl;
                const int bcol = wn + nt * 16;
                wmma::load_matrix_sync(bh, Bh + kk * LDB + bcol, LDB);
                wmma::load_matrix_sync(bl, Bl + kk * LDB + bcol, LDB);
#pragma unroll
                for (int mt = 0; mt < 2; mt++) {
                    wmma::mma_sync(acc[mt][nt], ah[mt], bh, acc[mt][nt]);
                    wmma::mma_sync(acc[mt][nt], al[mt], bh, acc[mt][nt]);
                    wmma::mma_sync(acc[mt][nt], ah[mt], bl, acc[mt][nt]);
                }
            }
        }
        __syncthreads();
    }

    // weighted scatter via per-warp staging
    float* stg = (float*)sm + wid * 320;   // 16x20 per warp
#pragma unroll
    for (int mt = 0; mt < 2; mt++)
#pragma unroll
        for (int nt = 0; nt < 2; nt++) {
            wmma::store_matrix_sync(stg, acc[mt][nt], 20, wmma::mem_row_major);
            __syncwarp();
            for (int i = lane; i < 256; i += 32) {
                int r = i >> 4, c = i & 15;
                int m = m0 + wm + mt * 16 + r;
                if (m < cnt) {
                    int   t = g_tok[base + m];
                    float w = g_w[base + m];
                    atomicAdd(out + (size_t)t * HIDDEN + n0 + wn + nt * 16 + c,
                              w * stg[r * 20 + c]);
                }
            }
            __syncwarp();
        }
}

// ---------------- launch --------------------------------------------------------
extern "C" void kernel_launch(void* const* d_in, const int* in_sizes, int n_in,
                              void* d_out, int out_size) {
    (void)in_sizes; (void)n_in; (void)out_size;
    const float* hidden = (const float*)d_in[0];
    const float* logits = (const float*)d_in[1];
    const float* wg     = (const float*)d_in[2];
    const float* wu     = (const float*)d_in[3];
    const float* wd     = (const float*)d_in[4];
    float* out = (float*)d_out;

    zero_kernel<<<(TOKENS * HIDDEN + 255) / 256, 256>>>(out);           // 0
    route_kernel<<<(TOKENS + 255) / 256, 256>>>(logits);                // 1
    scan_kernel<<<1, 32>>>();                                           // 2
    place_kernel<<<(TOKENS + 255) / 256, 256>>>();                      // 3

    dim3 g1(INTER / 64, (TOKENS + 127) / 128, NE);   // (22, 32, 16)
    gemm1_wmma<<<g1, 256, G1_SMEM>>>(hidden, wg, wu);                   // 4

    dim3 g2(HIDDEN / 64, (TOKENS + 127) / 128, NE);  // (32, 32, 16)
    gemm2_wmma<<<g2, 256, G2_SMEM>>>(wd, out);                          // 5
}